// round 7
// baseline (speedup 1.0000x reference)
#include <cuda_runtime.h>
#include <cstdint>

#define NCTA_PER_CLUSTER 4
#define BC        4      // batch elements per cluster
#define HID       128
#define NTHREADS  256
#define NWIN      252    // total prediction steps = T - WS
#define TT        256    // trajectory length
#define PADH      132    // padded row stride (132 % 32 == 4 -> conflict-free)
#define LROWS     128    // local gate rows per CTA (32 units x 4 gates)

struct Smem {
    float Wih1s[LROWS * PADH];
    float Whh1s[LROWS * PADH];
    float Whh0s[LROWS * PADH];
    float Wih0s[LROWS * 4];
    float h0[BC * PADH];
    float h1[BC * PADH];
    float c0[BC * PADH];
    float c1[BC * PADH];
    float gates[BC * PADH];
    float xin[4 * BC * 4];     // [t][b][f(pad4)]
    float b0s[LROWS];
    float b1s[LROWS];
    float Wl[2 * HID];
    float winbuf[BC * 4 * 2];  // [b][j][o] last 4 predictions
    float pred[BC * 2];
    float bl[2];
};

__device__ __forceinline__ void cluster_sync_all() {
    asm volatile("barrier.cluster.arrive.aligned;" ::: "memory");
    asm volatile("barrier.cluster.wait.aligned;" ::: "memory");
}

__device__ __forceinline__ float sigf(float x) {
    return 1.0f / (1.0f + __expf(-x));
}

// acc += W[r0,:] . v  and  W[r0+64,:] . v   (K = 128, float4 smem loads)
__device__ __forceinline__ void dot_rows(const float* __restrict__ W,
                                         const float* __restrict__ v,
                                         float& a0, float& a1, int r0) {
    const float4* w0 = reinterpret_cast<const float4*>(W + r0 * PADH);
    const float4* w1 = reinterpret_cast<const float4*>(W + (r0 + 64) * PADH);
    const float4* vp = reinterpret_cast<const float4*>(v);
#pragma unroll
    for (int k = 0; k < 32; k++) {
        float4 hv = vp[k];
        float4 x0 = w0[k];
        float4 x1 = w1[k];
        a0 = fmaf(x0.x, hv.x, a0); a0 = fmaf(x0.y, hv.y, a0);
        a0 = fmaf(x0.z, hv.z, a0); a0 = fmaf(x0.w, hv.w, a0);
        a1 = fmaf(x1.x, hv.x, a1); a1 = fmaf(x1.y, hv.y, a1);
        a1 = fmaf(x1.z, hv.z, a1); a1 = fmaf(x1.w, hv.w, a1);
    }
}

// gates -> activations -> new c (local), new h pushed to all 4 cluster CTAs
__device__ __forceinline__ void act_and_push(Smem& s, float* cbuf, float* hbuf,
                                             bool first, int rank, int tid) {
    if (tid < 128) {
        int b = tid >> 5, u = tid & 31;
        int j = rank * 32 + u;
        const float* g = s.gates + b * PADH;
        float vi = sigf(g[u]);
        float vf = sigf(g[32 + u]);
        float vg = tanhf(g[64 + u]);
        float vo = sigf(g[96 + u]);
        float cc = vi * vg;
        if (!first) cc = fmaf(vf, cbuf[b * PADH + j], cc);
        cbuf[b * PADH + j] = cc;
        float hh = vo * tanhf(cc);
        uint32_t laddr = (uint32_t)__cvta_generic_to_shared(&hbuf[b * PADH + j]);
#pragma unroll
        for (int r = 0; r < NCTA_PER_CLUSTER; r++) {
            uint32_t ra;
            asm volatile("mapa.shared::cluster.u32 %0, %1, %2;"
                         : "=r"(ra) : "r"(laddr), "r"(r));
            asm volatile("st.shared::cluster.f32 [%0], %1;"
                         :: "r"(ra), "f"(hh) : "memory");
        }
    }
}

extern __shared__ float smem_raw[];

__global__ void __cluster_dims__(NCTA_PER_CLUSTER, 1, 1) __launch_bounds__(NTHREADS, 1)
lstm_kernel(const float* __restrict__ traj,
            const float* __restrict__ Wih0, const float* __restrict__ Whh0,
            const float* __restrict__ bih0, const float* __restrict__ bhh0,
            const float* __restrict__ Wih1, const float* __restrict__ Whh1,
            const float* __restrict__ bih1, const float* __restrict__ bhh1,
            const float* __restrict__ Wl,   const float* __restrict__ bl,
            float* __restrict__ out) {
    Smem& s = *reinterpret_cast<Smem*>(smem_raw);
    const int tid = threadIdx.x;
    uint32_t rank;
    asm("mov.u32 %0, %%cluster_ctarank;" : "=r"(rank));
    const int cluster = blockIdx.x / NCTA_PER_CLUSTER;
    const int gb0 = cluster * BC;

    // ---- load weight slices: local row lr = g*32+u  <->  global row g*128 + rank*32 + u
    for (int i = tid; i < LROWS * HID; i += NTHREADS) {
        int lr = i / HID, k = i % HID;
        int g = lr >> 5, u = lr & 31;
        int gr = g * 128 + (int)rank * 32 + u;
        s.Whh0s[lr * PADH + k] = Whh0[gr * HID + k];
        s.Wih1s[lr * PADH + k] = Wih1[gr * HID + k];
        s.Whh1s[lr * PADH + k] = Whh1[gr * HID + k];
    }
    for (int lr = tid; lr < LROWS; lr += NTHREADS) {
        int g = lr >> 5, u = lr & 31;
        int gr = g * 128 + (int)rank * 32 + u;
        s.Wih0s[lr * 4 + 0] = Wih0[gr * 3 + 0];
        s.Wih0s[lr * 4 + 1] = Wih0[gr * 3 + 1];
        s.Wih0s[lr * 4 + 2] = Wih0[gr * 3 + 2];
        s.Wih0s[lr * 4 + 3] = 0.0f;
        s.b0s[lr] = bih0[gr] + bhh0[gr];
        s.b1s[lr] = bih1[gr] + bhh1[gr];
    }
    for (int i = tid; i < 2 * HID; i += NTHREADS) s.Wl[i] = Wl[i];
    if (tid < 2) s.bl[tid] = bl[tid];
    __syncthreads();
    cluster_sync_all();

    const int b_of = tid & 3;       // batch within cluster
    const int r0   = tid >> 2;      // 0..63 -> rows r0, r0+64

    for (int w = 0; w < NWIN; w++) {
        // ---- build window input xin[t][b][f]
        if (tid < 64) {
            int t = tid >> 4, b = (tid >> 2) & 3, f = tid & 3;
            if (f < 3) {
                int gb = gb0 + b;
                float v;
                if (w == 0) {
                    v = traj[(gb * TT + t) * 3 + f];
                } else if (w < 4) {
                    if (t < 3) v = traj[(gb * TT + (w + t)) * 3 + f];
                    else v = (f == 0) ? traj[(gb * TT + (4 + w)) * 3 + 0]
                                      : s.winbuf[(b * 4 + 3) * 2 + (f - 1)];
                } else {
                    v = (f < 2) ? s.winbuf[(b * 4 + t) * 2 + f]
                                : traj[(gb * TT + (w + t)) * 3 + 0];
                }
                s.xin[(t * 4 + b) * 4 + f] = v;
            }
        }
        __syncthreads();

        for (int t = 0; t < 4; t++) {
            const bool first = (t == 0);
            // ---- layer 0 gates = Wih0 @ x[t] + Whh0 @ h0 + b0
            {
                float a0 = s.b0s[r0], a1 = s.b0s[r0 + 64];
                const float* x = &s.xin[(t * 4 + b_of) * 4];
                float x0 = x[0], x1 = x[1], x2 = x[2];
                const float* wr0 = &s.Wih0s[r0 * 4];
                const float* wr1 = &s.Wih0s[(r0 + 64) * 4];
                a0 = fmaf(wr0[0], x0, fmaf(wr0[1], x1, fmaf(wr0[2], x2, a0)));
                a1 = fmaf(wr1[0], x0, fmaf(wr1[1], x1, fmaf(wr1[2], x2, a1)));
                if (!first) dot_rows(s.Whh0s, &s.h0[b_of * PADH], a0, a1, r0);
                s.gates[b_of * PADH + r0]      = a0;
                s.gates[b_of * PADH + r0 + 64] = a1;
            }
            __syncthreads();
            act_and_push(s, s.c0, s.h0, first, (int)rank, tid);
            cluster_sync_all();

            // ---- layer 1 gates = Wih1 @ h0[t] + Whh1 @ h1 + b1
            {
                float a0 = s.b1s[r0], a1 = s.b1s[r0 + 64];
                dot_rows(s.Wih1s, &s.h0[b_of * PADH], a0, a1, r0);
                if (!first) dot_rows(s.Whh1s, &s.h1[b_of * PADH], a0, a1, r0);
                s.gates[b_of * PADH + r0]      = a0;
                s.gates[b_of * PADH + r0 + 64] = a1;
            }
            __syncthreads();
            act_and_push(s, s.c1, s.h1, first, (int)rank, tid);
            cluster_sync_all();
        }

        // ---- head: pred[b][o] = Wl[o,:] . h1[b,:] + bl[o]  (8 warps, warp reduce)
        {
            int wid = tid >> 5, lane = tid & 31;
            int b = wid >> 1, o = wid & 1;
            const float4* wl4 = reinterpret_cast<const float4*>(&s.Wl[o * HID]);
            const float4* h4  = reinterpret_cast<const float4*>(&s.h1[b * PADH]);
            float4 a = wl4[lane], hh = h4[lane];
            float p = a.x * hh.x + a.y * hh.y + a.z * hh.z + a.w * hh.w;
            p += __shfl_xor_sync(0xFFFFFFFFu, p, 16);
            p += __shfl_xor_sync(0xFFFFFFFFu, p, 8);
            p += __shfl_xor_sync(0xFFFFFFFFu, p, 4);
            p += __shfl_xor_sync(0xFFFFFFFFu, p, 2);
            p += __shfl_xor_sync(0xFFFFFFFFu, p, 1);
            if (lane == 0) s.pred[b * 2 + o] = p + s.bl[o];
        }
        __syncthreads();
        if (tid < 8) {
            int b = tid >> 1, o = tid & 1;
            int gb = gb0 + b;
            float base = (w < 4) ? traj[(gb * TT + 3 + w) * 3 + 1 + o]
                                 : s.winbuf[(b * 4 + 3) * 2 + o];
            float pn = base + s.pred[b * 2 + o];
            float t1 = s.winbuf[(b * 4 + 1) * 2 + o];
            float t2 = s.winbuf[(b * 4 + 2) * 2 + o];
            float t3 = s.winbuf[(b * 4 + 3) * 2 + o];
            s.winbuf[(b * 4 + 0) * 2 + o] = t1;
            s.winbuf[(b * 4 + 1) * 2 + o] = t2;
            s.winbuf[(b * 4 + 2) * 2 + o] = t3;
            s.winbuf[(b * 4 + 3) * 2 + o] = pn;
            if (rank == 0) out[(gb * NWIN + w) * 2 + o] = pn;
        }
        __syncthreads();
    }

    // ---- final hidden/cell states: each CTA writes its own 32-unit slice
    if (tid < 128) {
        int b = tid >> 5, u = tid & 31;
        int j = (int)rank * 32 + u;
        int gb = gb0 + b;
        const int OFF_H = 128 * NWIN * 2;        // 64512
        const int OFF_C = OFF_H + 2 * 128 * HID; // 97280
        out[OFF_H + 0 * 128 * HID + gb * HID + j] = s.h0[b * PADH + j];
        out[OFF_H + 1 * 128 * HID + gb * HID + j] = s.h1[b * PADH + j];
        out[OFF_C + 0 * 128 * HID + gb * HID + j] = s.c0[b * PADH + j];
        out[OFF_C + 1 * 128 * HID + gb * HID + j] = s.c1[b * PADH + j];
    }
}

extern "C" void kernel_launch(void* const* d_in, const int* in_sizes, int n_in,
                              void* d_out, int out_size) {
    const float* traj = (const float*)d_in[0];
    const float* Wih0 = (const float*)d_in[1];
    const float* Whh0 = (const float*)d_in[2];
    const float* bih0 = (const float*)d_in[3];
    const float* bhh0 = (const float*)d_in[4];
    const float* Wih1 = (const float*)d_in[5];
    const float* Whh1 = (const float*)d_in[6];
    const float* bih1 = (const float*)d_in[7];
    const float* bhh1 = (const float*)d_in[8];
    const float* Wl   = (const float*)d_in[9];
    const float* bl   = (const float*)d_in[10];
    float* out = (float*)d_out;

    int smem = (int)sizeof(Smem);
    cudaFuncSetAttribute(lstm_kernel, cudaFuncAttributeMaxDynamicSharedMemorySize, smem);
    lstm_kernel<<<128, NTHREADS, smem>>>(traj, Wih0, Whh0, bih0, bhh0,
                                         Wih1, Whh1, bih1, bhh1, Wl, bl, out);
}